// round 15
// baseline (speedup 1.0000x reference)
#include <cuda_runtime.h>
#include <cuda_bf16.h>
#include <math_constants.h>

#define B_  8
#define SQ_ 128
#define SK_ 1024
#define U_  256

// Scratch: projections in MIXED layout.
// u%8 in {0,1}: raw value x. u%8 in {2..7}: e^{2x} (for exp identity).
__device__ float g_q[B_ * SQ_ * U_];   // 1 MB
__device__ float g_k[B_ * SK_ * U_];   // 8 MB

__device__ __forceinline__ float tanha(float x) {
    float y;
    asm("tanh.approx.f32 %0, %1;" : "=f"(y) : "f"(x));
    return y;
}

// e^{2x} via MUFU ex2: 2^{x * 2*log2(e)}
__device__ __forceinline__ float exp2x(float x) {
    float y;
    float t = x * 2.8853900817779268f;
    asm("ex2.approx.f32 %0, %1;" : "=f"(y) : "f"(t));
    return y;
}

// Division-free reciprocal: magic-constant seed (ALU) + 2 Newton (FMA pipe).
__device__ __forceinline__ float rcp_fma(float den) {
    float y = __uint_as_float(0x7EF311C3u - __float_as_uint(den));
    y = y * (2.0f - den * y);
    y = y * (2.0f - den * y);
    return y;
}

__device__ __forceinline__ unsigned smem_u32(const void* p) {
    return (unsigned)__cvta_generic_to_shared(p);
}

// ---------------------------------------------------------------------------
// bf16 3-term split GEMM helpers
// ---------------------------------------------------------------------------
__device__ __forceinline__ void split_store8(float4 v,
                                             __nv_bfloat16* ph, __nv_bfloat16* pl) {
    __nv_bfloat162 h01 = __floats2bfloat162_rn(v.x, v.y);
    __nv_bfloat162 h23 = __floats2bfloat162_rn(v.z, v.w);
    __nv_bfloat162 l01 = __floats2bfloat162_rn(v.x - __bfloat162float(h01.x),
                                               v.y - __bfloat162float(h01.y));
    __nv_bfloat162 l23 = __floats2bfloat162_rn(v.z - __bfloat162float(h23.x),
                                               v.w - __bfloat162float(h23.y));
    *reinterpret_cast<__nv_bfloat162*>(ph)     = h01;
    *reinterpret_cast<__nv_bfloat162*>(ph + 2) = h23;
    *reinterpret_cast<__nv_bfloat162*>(pl)     = l01;
    *reinterpret_cast<__nv_bfloat162*>(pl + 2) = l23;
}

__device__ __forceinline__ void ldsm_x4(unsigned r[4], unsigned addr) {
    asm volatile("ldmatrix.sync.aligned.m8n8.x4.shared.b16 {%0,%1,%2,%3}, [%4];"
        : "=r"(r[0]), "=r"(r[1]), "=r"(r[2]), "=r"(r[3]) : "r"(addr));
}

__device__ __forceinline__ void ldsm_x4_t(unsigned r[4], unsigned addr) {
    asm volatile("ldmatrix.sync.aligned.m8n8.x4.trans.shared.b16 {%0,%1,%2,%3}, [%4];"
        : "=r"(r[0]), "=r"(r[1]), "=r"(r[2]), "=r"(r[3]) : "r"(addr));
}

__device__ __forceinline__ void mma_bf16(float* d, const unsigned a[4],
                                         unsigned b0, unsigned b1) {
    asm volatile("mma.sync.aligned.m16n8k16.row.col.f32.bf16.bf16.f32 "
        "{%0,%1,%2,%3}, {%4,%5,%6,%7}, {%8,%9}, {%0,%1,%2,%3};"
        : "+f"(d[0]), "+f"(d[1]), "+f"(d[2]), "+f"(d[3])
        : "r"(a[0]), "r"(a[1]), "r"(a[2]), "r"(a[3]), "r"(b0), "r"(b1));
}

// ---------------------------------------------------------------------------
// Tensor-core SGEMM, bf16 3-term split. MIXEPI=1: exp-transform cols with
// col%8 in {2..7}: tig==0 -> none; tig in {1,2,3} -> all four elems.
// ---------------------------------------------------------------------------
template <int IM, int MIXEPI>
__global__ void gemm_tc(const float* __restrict__ A, const float* __restrict__ Bm,
                        float* __restrict__ C, int M, int N, int K,
                        long long sA, long long sB, long long sC) {
    constexpr int TM = 32 * IM;
    A  += (long long)blockIdx.z * sA;
    Bm += (long long)blockIdx.z * sB;
    C  += (long long)blockIdx.z * sC;

    __shared__ alignas(16) __nv_bfloat16 Ah[TM][40], Al[TM][40];
    __shared__ alignas(16) __nv_bfloat16 Bh[32][72], Bl[32][72];

    const int tid  = threadIdx.x;
    const int lane = tid & 31;
    const int warp = tid >> 5;
    const int wm   = warp >> 2;
    const int wn   = warp & 3;
    const int gid  = lane >> 2;
    const int tig  = lane & 3;
    const int m_base = wm * (16 * IM);
    const int n_base = wn * 16;
    const int m0 = blockIdx.y * TM;
    const int n0 = blockIdx.x * 64;

    const int l8   = lane & 7;
    const int t8   = lane >> 3;
    const int rrow = l8 + ((t8 & 1) << 3);
    const int rcol = (t8 >> 1) << 3;

    const unsigned baseAh = smem_u32(&Ah[0][0]);
    const unsigned baseAl = smem_u32(&Al[0][0]);
    const unsigned baseBh = smem_u32(&Bh[0][0]);
    const unsigned baseBl = smem_u32(&Bl[0][0]);

    float acc[IM][2][4];
#pragma unroll
    for (int im = 0; im < IM; im++)
#pragma unroll
        for (int in = 0; in < 2; in++)
#pragma unroll
            for (int c = 0; c < 4; c++) acc[im][in][c] = 0.0f;

    for (int k0 = 0; k0 < K; k0 += 32) {
#pragma unroll
        for (int it = 0; it < IM; it++) {
            int idx = tid + it * 256;
            int r = idx >> 3;
            int c = (idx & 7) << 2;
            float4 v = *(const float4*)&A[(long long)(m0 + r) * K + k0 + c];
            split_store8(v, &Ah[r][c], &Al[r][c]);
        }
#pragma unroll
        for (int it = 0; it < 2; it++) {
            int idx = tid + it * 256;
            int r = idx >> 4;
            int c = (idx & 15) << 2;
            float4 v = *(const float4*)&Bm[(long long)(k0 + r) * N + n0 + c];
            split_store8(v, &Bh[r][c], &Bl[r][c]);
        }
        __syncthreads();

#pragma unroll
        for (int kk = 0; kk < 2; kk++) {
            const int kb = kk << 4;
            unsigned ah[IM][4], al[IM][4], bh[4], bl[4];
#pragma unroll
            for (int im = 0; im < IM; im++) {
                unsigned ra = ((unsigned)((m_base + 16 * im + rrow) * 40 + kb + rcol)) << 1;
                ldsm_x4(ah[im], baseAh + ra);
                ldsm_x4(al[im], baseAl + ra);
            }
            unsigned rb = ((unsigned)((kb + rrow) * 72 + n_base + rcol)) << 1;
            ldsm_x4_t(bh, baseBh + rb);
            ldsm_x4_t(bl, baseBl + rb);

#pragma unroll
            for (int im = 0; im < IM; im++) {
                mma_bf16(acc[im][0], ah[im], bh[0], bh[1]);
                mma_bf16(acc[im][0], ah[im], bl[0], bl[1]);
                mma_bf16(acc[im][0], al[im], bh[0], bh[1]);
                mma_bf16(acc[im][1], ah[im], bh[2], bh[3]);
                mma_bf16(acc[im][1], ah[im], bl[2], bl[3]);
                mma_bf16(acc[im][1], al[im], bh[2], bh[3]);
            }
        }
        __syncthreads();
    }

    // MIXEPI: thread tig holds cols {2*tig, 2*tig+1} (mod 8).
    // exp set {2..7}: tig==0 -> raw; tig in {1,2,3} -> exp all four.
#pragma unroll
    for (int im = 0; im < IM; im++) {
#pragma unroll
        for (int in = 0; in < 2; in++) {
            int row = m0 + m_base + 16 * im + gid;
            int col = n0 + n_base + 8 * in + 2 * tig;
            float* d = acc[im][in];
            if (MIXEPI && tig != 0) {
                d[0] = exp2x(d[0]);
                d[1] = exp2x(d[1]);
                d[2] = exp2x(d[2]);
                d[3] = exp2x(d[3]);
            }
            *(float2*)&C[(long long)row * N + col]       = make_float2(d[0], d[1]);
            *(float2*)&C[(long long)(row + 8) * N + col] = make_float2(d[2], d[3]);
        }
    }
}

// ---------------------------------------------------------------------------
// Scores v10 (2:6 MUFU/exp split): u%8 in {0,1} -> MUFU tanh(q+k).
// u%8 in {2..7} stored as E=e^{2x}:
//   tanh(q+k) = 1 - 2/(Eq*Ek + 1)
// -> fma + Newton-rcp + fma per element (0 MUFU; den >= 1, no cancellation).
// "+w" constants folded into cst at accumulator init.
// ---------------------------------------------------------------------------
#define TQ 16

__global__ void scores_kernel(const float* __restrict__ wv, float* __restrict__ attn) {
    const int b  = blockIdx.z;
    const int ib = blockIdx.y;
    const int tid = threadIdx.x;
    const int j  = blockIdx.x * 256 + tid;

    __shared__ float qs[TQ][U_];   // 16 KB (mixed layout)
    __shared__ float wvs[U_];

    const float* qbase = g_q + ((long long)(b * SQ_ + ib * TQ)) * U_;
#pragma unroll
    for (int l = 0; l < 4; l++) {
        int idx = tid + l * 256;
        int row = idx >> 6;
        int col = (idx & 63) << 2;
        *(float4*)&qs[row][col] = *(const float4*)&qbase[(long long)row * U_ + col];
    }
    if (tid < 64) *(float4*)&wvs[tid << 2] = *(const float4*)&wv[tid << 2];
    __syncthreads();

    // Constant part of the exp identity: sum of w over exp-set components.
    float cst = 0.0f;
#pragma unroll
    for (int c = 0; c < U_; c += 8)
        cst += wvs[c + 2] + wvs[c + 3] + wvs[c + 4] +
               wvs[c + 5] + wvs[c + 6] + wvs[c + 7];

    const float* kp = g_k + ((long long)(b * SK_) + j) * U_;

    float acc[TQ];
#pragma unroll
    for (int i = 0; i < TQ; i++) acc[i] = cst;

    float4 ka = *(const float4*)&kp[0];
    float4 kb = *(const float4*)&kp[4];

    for (int uc = 0; uc < U_; uc += 8) {
        int un = (uc + 8 < U_) ? uc + 8 : uc;   // clamped tail prefetch
        float4 kna = *(const float4*)&kp[un];
        float4 knb = *(const float4*)&kp[un + 4];
        float4 w0 = *(const float4*)&wvs[uc];
        float4 w1 = *(const float4*)&wvs[uc + 4];
        // prescaled exp-path weights (amortized over the i loop)
        float w2a = -2.0f * w0.z;
        float w2b = -2.0f * w0.w;
        float w2c = -2.0f * w1.x;
        float w2d = -2.0f * w1.y;
        float w2e = -2.0f * w1.z;
        float w2f = -2.0f * w1.w;
#pragma unroll
        for (int i = 0; i < TQ; i++) {
            float4 q0 = *(const float4*)&qs[i][uc];        // broadcast LDS
            float4 q1 = *(const float4*)&qs[i][uc + 4];
            float a = acc[i];
            // MUFU path (raw components: u%8 in {0,1})
            a = fmaf(tanha(q0.x + ka.x), w0.x, a);
            a = fmaf(tanha(q0.y + ka.y), w0.y, a);
            // exp path (E-components: u%8 in {2..7}); den = Eq*Ek + 1 >= 1
            a = fmaf(w2a, rcp_fma(fmaf(q0.z, ka.z, 1.0f)), a);
            a = fmaf(w2b, rcp_fma(fmaf(q0.w, ka.w, 1.0f)), a);
            a = fmaf(w2c, rcp_fma(fmaf(q1.x, kb.x, 1.0f)), a);
            a = fmaf(w2d, rcp_fma(fmaf(q1.y, kb.y, 1.0f)), a);
            a = fmaf(w2e, rcp_fma(fmaf(q1.z, kb.z, 1.0f)), a);
            a = fmaf(w2f, rcp_fma(fmaf(q1.w, kb.w, 1.0f)), a);
            acc[i] = a;
        }
        ka = kna;
        kb = knb;
    }

    long long base = ((long long)(b * SQ_ + ib * TQ)) * SK_ + j;
#pragma unroll
    for (int i = 0; i < TQ; i++) attn[base + (long long)i * SK_] = acc[i];
}

// ---------------------------------------------------------------------------
// Row softmax over SK=1024, in place. One CTA (256 threads) per (b,i) row.
// ---------------------------------------------------------------------------
__global__ void softmax_kernel(float* __restrict__ attn) {
    float* p = attn + (long long)blockIdx.x * SK_;
    const int tid = threadIdx.x;
    __shared__ float red[8];

    float4 x = *(const float4*)&p[tid << 2];
    float m = fmaxf(fmaxf(x.x, x.y), fmaxf(x.z, x.w));
#pragma unroll
    for (int o = 16; o; o >>= 1) m = fmaxf(m, __shfl_xor_sync(0xffffffffu, m, o));
    if ((tid & 31) == 0) red[tid >> 5] = m;
    __syncthreads();
    float M = red[0];
#pragma unroll
    for (int w = 1; w < 8; w++) M = fmaxf(M, red[w]);

    float4 e;
    e.x = __expf(x.x - M);
    e.y = __expf(x.y - M);
    e.z = __expf(x.z - M);
    e.w = __expf(x.w - M);
    float s = (e.x + e.y) + (e.z + e.w);
#pragma unroll
    for (int o = 16; o; o >>= 1) s += __shfl_xor_sync(0xffffffffu, s, o);
    __syncthreads();
    if ((tid & 31) == 0) red[tid >> 5] = s;
    __syncthreads();
    float S = 0.f;
#pragma unroll
    for (int w = 0; w < 8; w++) S += red[w];
    float inv = 1.0f / S;
    e.x *= inv; e.y *= inv; e.z *= inv; e.w *= inv;
    *(float4*)&p[tid << 2] = e;
}

// ---------------------------------------------------------------------------
extern "C" void kernel_launch(void* const* d_in, const int* in_sizes, int n_in,
                              void* d_out, int out_size) {
    const float* query = (const float*)d_in[0];
    const float* key   = (const float*)d_in[1];
    const float* value = (const float*)d_in[2];
    const float* Wq    = (const float*)d_in[3];
    const float* Wk    = (const float*)d_in[4];
    const float* wv    = (const float*)d_in[5];

    float* out  = (float*)d_out;
    float* ctx  = out;                            // [B, SQ, U]
    float* attn = out + (long long)B_ * SQ_ * U_; // [B, SQ, SK]

    void* pq = nullptr; void* pk = nullptr;
    cudaGetSymbolAddress(&pq, g_q);
    cudaGetSymbolAddress(&pk, g_k);
    float* dq = (float*)pq;
    float* dk = (float*)pk;

    // 1) Projections on tensor cores, MIXED epilogue (exp on u%8 in {2..7})
    gemm_tc<2, 1><<<dim3(U_ / 64, (B_ * SQ_) / 64, 1), 256>>>(
        query, Wq, dq, B_ * SQ_, U_, U_, 0, 0, 0);
    gemm_tc<2, 1><<<dim3(U_ / 64, (B_ * SK_) / 64, 1), 256>>>(
        key, Wk, dk, B_ * SK_, U_, U_, 0, 0, 0);

    // 2) Raw scores (2:6 MUFU/exp split) into attn region
    scores_kernel<<<dim3(SK_ / 256, SQ_ / TQ, B_), 256>>>(wv, attn);

    // 3) Softmax in place
    softmax_kernel<<<B_ * SQ_, 256>>>(attn);

    // 4) context = attn @ value (batched, plain epilogue)
    gemm_tc<1, 0><<<dim3(U_ / 64, SQ_ / 32, B_), 256>>>(
        attn, value, ctx, SQ_, U_, SK_,
        (long long)SQ_ * SK_, (long long)SK_ * U_, (long long)SQ_ * U_);
}

// round 16
// speedup vs baseline: 1.0926x; 1.0926x over previous
#include <cuda_runtime.h>
#include <cuda_bf16.h>
#include <math_constants.h>

#define B_  8
#define SQ_ 128
#define SK_ 1024
#define U_  256

// Scratch: projections in MIXED layout.
// u%8 in {0..3}: raw value x. u%8 in {4..7}: e^{2x} (for exp identity).
__device__ float g_q[B_ * SQ_ * U_];   // 1 MB
__device__ float g_k[B_ * SK_ * U_];   // 8 MB

__device__ __forceinline__ float tanha(float x) {
    float y;
    asm("tanh.approx.f32 %0, %1;" : "=f"(y) : "f"(x));
    return y;
}

// e^{2x} via MUFU ex2: 2^{x * 2*log2(e)}
__device__ __forceinline__ float exp2x(float x) {
    float y;
    float t = x * 2.8853900817779268f;
    asm("ex2.approx.f32 %0, %1;" : "=f"(y) : "f"(t));
    return y;
}

__device__ __forceinline__ unsigned smem_u32(const void* p) {
    return (unsigned)__cvta_generic_to_shared(p);
}

// ---------------------------------------------------------------------------
// bf16 3-term split GEMM helpers
// ---------------------------------------------------------------------------
__device__ __forceinline__ void split_store8(float4 v,
                                             __nv_bfloat16* ph, __nv_bfloat16* pl) {
    __nv_bfloat162 h01 = __floats2bfloat162_rn(v.x, v.y);
    __nv_bfloat162 h23 = __floats2bfloat162_rn(v.z, v.w);
    __nv_bfloat162 l01 = __floats2bfloat162_rn(v.x - __bfloat162float(h01.x),
                                               v.y - __bfloat162float(h01.y));
    __nv_bfloat162 l23 = __floats2bfloat162_rn(v.z - __bfloat162float(h23.x),
                                               v.w - __bfloat162float(h23.y));
    *reinterpret_cast<__nv_bfloat162*>(ph)     = h01;
    *reinterpret_cast<__nv_bfloat162*>(ph + 2) = h23;
    *reinterpret_cast<__nv_bfloat162*>(pl)     = l01;
    *reinterpret_cast<__nv_bfloat162*>(pl + 2) = l23;
}

__device__ __forceinline__ void ldsm_x4(unsigned r[4], unsigned addr) {
    asm volatile("ldmatrix.sync.aligned.m8n8.x4.shared.b16 {%0,%1,%2,%3}, [%4];"
        : "=r"(r[0]), "=r"(r[1]), "=r"(r[2]), "=r"(r[3]) : "r"(addr));
}

__device__ __forceinline__ void ldsm_x4_t(unsigned r[4], unsigned addr) {
    asm volatile("ldmatrix.sync.aligned.m8n8.x4.trans.shared.b16 {%0,%1,%2,%3}, [%4];"
        : "=r"(r[0]), "=r"(r[1]), "=r"(r[2]), "=r"(r[3]) : "r"(addr));
}

__device__ __forceinline__ void mma_bf16(float* d, const unsigned a[4],
                                         unsigned b0, unsigned b1) {
    asm volatile("mma.sync.aligned.m16n8k16.row.col.f32.bf16.bf16.f32 "
        "{%0,%1,%2,%3}, {%4,%5,%6,%7}, {%8,%9}, {%0,%1,%2,%3};"
        : "+f"(d[0]), "+f"(d[1]), "+f"(d[2]), "+f"(d[3])
        : "r"(a[0]), "r"(a[1]), "r"(a[2]), "r"(a[3]), "r"(b0), "r"(b1));
}

// ---------------------------------------------------------------------------
// Tensor-core SGEMM, bf16 3-term split. MIXEPI=1: exp-transform cols with
// col%8 in {4..7} (threads with tig >= 2 transform all four elements).
// ---------------------------------------------------------------------------
template <int IM, int MIXEPI>
__global__ void gemm_tc(const float* __restrict__ A, const float* __restrict__ Bm,
                        float* __restrict__ C, int M, int N, int K,
                        long long sA, long long sB, long long sC) {
    constexpr int TM = 32 * IM;
    A  += (long long)blockIdx.z * sA;
    Bm += (long long)blockIdx.z * sB;
    C  += (long long)blockIdx.z * sC;

    __shared__ alignas(16) __nv_bfloat16 Ah[TM][40], Al[TM][40];
    __shared__ alignas(16) __nv_bfloat16 Bh[32][72], Bl[32][72];

    const int tid  = threadIdx.x;
    const int lane = tid & 31;
    const int warp = tid >> 5;
    const int wm   = warp >> 2;
    const int wn   = warp & 3;
    const int gid  = lane >> 2;
    const int tig  = lane & 3;
    const int m_base = wm * (16 * IM);
    const int n_base = wn * 16;
    const int m0 = blockIdx.y * TM;
    const int n0 = blockIdx.x * 64;

    const int l8   = lane & 7;
    const int t8   = lane >> 3;
    const int rrow = l8 + ((t8 & 1) << 3);
    const int rcol = (t8 >> 1) << 3;

    const unsigned baseAh = smem_u32(&Ah[0][0]);
    const unsigned baseAl = smem_u32(&Al[0][0]);
    const unsigned baseBh = smem_u32(&Bh[0][0]);
    const unsigned baseBl = smem_u32(&Bl[0][0]);

    float acc[IM][2][4];
#pragma unroll
    for (int im = 0; im < IM; im++)
#pragma unroll
        for (int in = 0; in < 2; in++)
#pragma unroll
            for (int c = 0; c < 4; c++) acc[im][in][c] = 0.0f;

    for (int k0 = 0; k0 < K; k0 += 32) {
#pragma unroll
        for (int it = 0; it < IM; it++) {
            int idx = tid + it * 256;
            int r = idx >> 3;
            int c = (idx & 7) << 2;
            float4 v = *(const float4*)&A[(long long)(m0 + r) * K + k0 + c];
            split_store8(v, &Ah[r][c], &Al[r][c]);
        }
#pragma unroll
        for (int it = 0; it < 2; it++) {
            int idx = tid + it * 256;
            int r = idx >> 4;
            int c = (idx & 15) << 2;
            float4 v = *(const float4*)&Bm[(long long)(k0 + r) * N + n0 + c];
            split_store8(v, &Bh[r][c], &Bl[r][c]);
        }
        __syncthreads();

#pragma unroll
        for (int kk = 0; kk < 2; kk++) {
            const int kb = kk << 4;
            unsigned ah[IM][4], al[IM][4], bh[4], bl[4];
#pragma unroll
            for (int im = 0; im < IM; im++) {
                unsigned ra = ((unsigned)((m_base + 16 * im + rrow) * 40 + kb + rcol)) << 1;
                ldsm_x4(ah[im], baseAh + ra);
                ldsm_x4(al[im], baseAl + ra);
            }
            unsigned rb = ((unsigned)((kb + rrow) * 72 + n_base + rcol)) << 1;
            ldsm_x4_t(bh, baseBh + rb);
            ldsm_x4_t(bl, baseBl + rb);

#pragma unroll
            for (int im = 0; im < IM; im++) {
                mma_bf16(acc[im][0], ah[im], bh[0], bh[1]);
                mma_bf16(acc[im][0], ah[im], bl[0], bl[1]);
                mma_bf16(acc[im][0], al[im], bh[0], bh[1]);
                mma_bf16(acc[im][1], ah[im], bh[2], bh[3]);
                mma_bf16(acc[im][1], ah[im], bl[2], bl[3]);
                mma_bf16(acc[im][1], al[im], bh[2], bh[3]);
            }
        }
        __syncthreads();
    }

    // MIXEPI: thread tig holds cols {2*tig, 2*tig+1} (mod 8).
    // exp set {4..7}: tig in {2,3} -> exp all four elements.
#pragma unroll
    for (int im = 0; im < IM; im++) {
#pragma unroll
        for (int in = 0; in < 2; in++) {
            int row = m0 + m_base + 16 * im + gid;
            int col = n0 + n_base + 8 * in + 2 * tig;
            float* d = acc[im][in];
            if (MIXEPI && tig >= 2) {
                d[0] = exp2x(d[0]);
                d[1] = exp2x(d[1]);
                d[2] = exp2x(d[2]);
                d[3] = exp2x(d[3]);
            }
            *(float2*)&C[(long long)row * N + col]       = make_float2(d[0], d[1]);
            *(float2*)&C[(long long)(row + 8) * N + col] = make_float2(d[2], d[3]);
        }
    }
}

// ---------------------------------------------------------------------------
// Scores v11 (4:4 MUFU/exp, pairwise-combined rcp):
//   u%8 in {0..3}: raw -> MUFU tanh(q+k).
//   u%8 in {4..7}: stored as E=e^{2x}; tanh(q+k) = 1 - 2/(EqEk+1).
// Two exp elements share ONE Newton reciprocal:
//   w1/d1 + w2/d2 = (w1*d2 + w2*d1) / (d1*d2)
// -> 10 FMA-pipe ops per pair (C_eff = 5 per element), 0 MUFU.
// "+w" constants folded into cst at accumulator init.
// ---------------------------------------------------------------------------
#define TQ 16

__global__ void scores_kernel(const float* __restrict__ wv, float* __restrict__ attn) {
    const int b  = blockIdx.z;
    const int ib = blockIdx.y;
    const int tid = threadIdx.x;
    const int j  = blockIdx.x * 256 + tid;

    __shared__ float qs[TQ][U_];   // 16 KB (mixed layout)
    __shared__ float wvs[U_];

    const float* qbase = g_q + ((long long)(b * SQ_ + ib * TQ)) * U_;
#pragma unroll
    for (int l = 0; l < 4; l++) {
        int idx = tid + l * 256;
        int row = idx >> 6;
        int col = (idx & 63) << 2;
        *(float4*)&qs[row][col] = *(const float4*)&qbase[(long long)row * U_ + col];
    }
    if (tid < 64) *(float4*)&wvs[tid << 2] = *(const float4*)&wv[tid << 2];
    __syncthreads();

    // Constant part of the exp identity: sum of w over exp-set components.
    float cst = 0.0f;
#pragma unroll
    for (int c = 0; c < U_; c += 8)
        cst += wvs[c + 4] + wvs[c + 5] + wvs[c + 6] + wvs[c + 7];

    const float* kp = g_k + ((long long)(b * SK_) + j) * U_;

    float acc[TQ];
#pragma unroll
    for (int i = 0; i < TQ; i++) acc[i] = cst;

    float4 ka = *(const float4*)&kp[0];
    float4 kb = *(const float4*)&kp[4];

    for (int uc = 0; uc < U_; uc += 8) {
        int un = (uc + 8 < U_) ? uc + 8 : uc;   // clamped tail prefetch
        float4 kna = *(const float4*)&kp[un];
        float4 knb = *(const float4*)&kp[un + 4];
        float4 w0 = *(const float4*)&wvs[uc];
        float4 w1 = *(const float4*)&wvs[uc + 4];
        // prescaled exp-path weights (amortized over the i loop)
        float w2a = -2.0f * w1.x;
        float w2b = -2.0f * w1.y;
        float w2c = -2.0f * w1.z;
        float w2d = -2.0f * w1.w;
#pragma unroll
        for (int i = 0; i < TQ; i++) {
            float4 q0 = *(const float4*)&qs[i][uc];        // broadcast LDS (raw)
            float4 q1 = *(const float4*)&qs[i][uc + 4];    // broadcast LDS (E)
            float a = acc[i];
            // MUFU path (raw components: u%8 in {0..3})
            a = fmaf(tanha(q0.x + ka.x), w0.x, a);
            a = fmaf(tanha(q0.y + ka.y), w0.y, a);
            a = fmaf(tanha(q0.z + ka.z), w0.z, a);
            a = fmaf(tanha(q0.w + ka.w), w0.w, a);
            // exp path: pair 1 = (u%8==4, u%8==5), pair 2 = (6, 7)
            {
                float d1 = fmaf(q1.x, kb.x, 1.0f);         // >= 1
                float d2 = fmaf(q1.y, kb.y, 1.0f);
                float p  = d1 * d2;
                float num = fmaf(w2a, d2, w2b * d1);
                float y = __uint_as_float(0x7EF311C3u - __float_as_uint(p));
                y = y * fmaf(-p, y, 2.0f);
                y = y * fmaf(-p, y, 2.0f);
                a = fmaf(num, y, a);
            }
            {
                float d1 = fmaf(q1.z, kb.z, 1.0f);
                float d2 = fmaf(q1.w, kb.w, 1.0f);
                float p  = d1 * d2;
                float num = fmaf(w2c, d2, w2d * d1);
                float y = __uint_as_float(0x7EF311C3u - __float_as_uint(p));
                y = y * fmaf(-p, y, 2.0f);
                y = y * fmaf(-p, y, 2.0f);
                a = fmaf(num, y, a);
            }
            acc[i] = a;
        }
        ka = kna;
        kb = knb;
    }

    long long base = ((long long)(b * SQ_ + ib * TQ)) * SK_ + j;
#pragma unroll
    for (int i = 0; i < TQ; i++) attn[base + (long long)i * SK_] = acc[i];
}

// ---------------------------------------------------------------------------
// Row softmax over SK=1024, in place. One CTA (256 threads) per (b,i) row.
// ---------------------------------------------------------------------------
__global__ void softmax_kernel(float* __restrict__ attn) {
    float* p = attn + (long long)blockIdx.x * SK_;
    const int tid = threadIdx.x;
    __shared__ float red[8];

    float4 x = *(const float4*)&p[tid << 2];
    float m = fmaxf(fmaxf(x.x, x.y), fmaxf(x.z, x.w));
#pragma unroll
    for (int o = 16; o; o >>= 1) m = fmaxf(m, __shfl_xor_sync(0xffffffffu, m, o));
    if ((tid & 31) == 0) red[tid >> 5] = m;
    __syncthreads();
    float M = red[0];
#pragma unroll
    for (int w = 1; w < 8; w++) M = fmaxf(M, red[w]);

    float4 e;
    e.x = __expf(x.x - M);
    e.y = __expf(x.y - M);
    e.z = __expf(x.z - M);
    e.w = __expf(x.w - M);
    float s = (e.x + e.y) + (e.z + e.w);
#pragma unroll
    for (int o = 16; o; o >>= 1) s += __shfl_xor_sync(0xffffffffu, s, o);
    __syncthreads();
    if ((tid & 31) == 0) red[tid >> 5] = s;
    __syncthreads();
    float S = 0.f;
#pragma unroll
    for (int w = 0; w < 8; w++) S += red[w];
    float inv = 1.0f / S;
    e.x *= inv; e.y *= inv; e.z *= inv; e.w *= inv;
    *(float4*)&p[tid << 2] = e;
}

// ---------------------------------------------------------------------------
extern "C" void kernel_launch(void* const* d_in, const int* in_sizes, int n_in,
                              void* d_out, int out_size) {
    const float* query = (const float*)d_in[0];
    const float* key   = (const float*)d_in[1];
    const float* value = (const float*)d_in[2];
    const float* Wq    = (const float*)d_in[3];
    const float* Wk    = (const float*)d_in[4];
    const float* wv    = (const float*)d_in[5];

    float* out  = (float*)d_out;
    float* ctx  = out;                            // [B, SQ, U]
    float* attn = out + (long long)B_ * SQ_ * U_; // [B, SQ, SK]

    void* pq = nullptr; void* pk = nullptr;
    cudaGetSymbolAddress(&pq, g_q);
    cudaGetSymbolAddress(&pk, g_k);
    float* dq = (float*)pq;
    float* dk = (float*)pk;

    // 1) Projections on tensor cores, MIXED epilogue (exp on u%8 in {4..7})
    gemm_tc<2, 1><<<dim3(U_ / 64, (B_ * SQ_) / 64, 1), 256>>>(
        query, Wq, dq, B_ * SQ_, U_, U_, 0, 0, 0);
    gemm_tc<2, 1><<<dim3(U_ / 64, (B_ * SK_) / 64, 1), 256>>>(
        key, Wk, dk, B_ * SK_, U_, U_, 0, 0, 0);

    // 2) Raw scores (4:4 MUFU/exp, pairwise rcp) into attn region
    scores_kernel<<<dim3(SK_ / 256, SQ_ / TQ, B_), 256>>>(wv, attn);

    // 3) Softmax in place
    softmax_kernel<<<B_ * SQ_, 256>>>(attn);

    // 4) context = attn @ value (batched, plain epilogue)
    gemm_tc<1, 0><<<dim3(U_ / 64, SQ_ / 32, B_), 256>>>(
        attn, value, ctx, SQ_, U_, SK_,
        (long long)SQ_ * SK_, (long long)SK_ * U_, (long long)SQ_ * U_);
}